// round 1
// baseline (speedup 1.0000x reference)
#include <cuda_runtime.h>
#include <math.h>

#define B_    8
#define C_    256
#define N_    1024
#define H_    8
#define D_    64
#define HID_  512
#define O3_   1536
#define SCALE_ 10.0f
#define EPS_   1e-12f

// Scratch (static device arrays; no allocation allowed)
__device__ float g_qkv[(size_t)B_ * O3_ * N_];   // [b][o][p], o in [0,1536): q,k,v stacked
__device__ float g_inv[2 * B_ * HID_];           // [which(q=0,k=1)][b][h*64+d]
__device__ float g_att[(size_t)B_ * HID_ * N_];  // [b][h*64+d][p] attention output

// ---------------------------------------------------------------------------
// Generic batched SGEMM: Y[b][o][p] = sum_c W[o][c] * X[b][c][p] (+bias[o])
// Block tile 64x64, K-tile 16, 256 threads, 4x4 register tile per thread.
// ---------------------------------------------------------------------------
template <int M, int K, bool BIAS>
__global__ void __launch_bounds__(256, 4) gemm_k(const float* __restrict__ W,
                                                 const float* __restrict__ X,
                                                 const float* __restrict__ bias,
                                                 float* __restrict__ Y)
{
    const int b  = blockIdx.z;
    const int o0 = blockIdx.y * 64;
    const int p0 = blockIdx.x * 64;
    const float* Xb = X + (size_t)b * K * N_;
    float*       Yb = Y + (size_t)b * M * N_;

    __shared__ float Ws[16][64];  // [c][o]
    __shared__ float Xs[16][64];  // [c][p]

    const int tid = threadIdx.x;
    const int ty = tid >> 4;      // 0..15 -> o groups of 4
    const int tx = tid & 15;      // 0..15 -> p groups of 4

    float acc[4][4];
#pragma unroll
    for (int r = 0; r < 4; r++)
#pragma unroll
        for (int c = 0; c < 4; c++) acc[r][c] = 0.f;

    for (int k0 = 0; k0 < K; k0 += 16) {
        // W tile: 64 o x 16 c
        {
            const int o  = tid >> 2;
            const int c4 = (tid & 3) * 4;
            float4 w4 = *(const float4*)(W + (size_t)(o0 + o) * K + k0 + c4);
            Ws[c4 + 0][o] = w4.x;
            Ws[c4 + 1][o] = w4.y;
            Ws[c4 + 2][o] = w4.z;
            Ws[c4 + 3][o] = w4.w;
        }
        // X tile: 16 c x 64 p
        {
            const int cc = tid >> 4;
            const int p4 = (tid & 15) * 4;
            *(float4*)&Xs[cc][p4] =
                *(const float4*)(Xb + (size_t)(k0 + cc) * N_ + p0 + p4);
        }
        __syncthreads();

#pragma unroll
        for (int c = 0; c < 16; c++) {
            float4 a  = *(const float4*)&Ws[c][ty * 4];
            float4 bb = *(const float4*)&Xs[c][tx * 4];
            float av[4] = {a.x, a.y, a.z, a.w};
            float bv[4] = {bb.x, bb.y, bb.z, bb.w};
#pragma unroll
            for (int r = 0; r < 4; r++)
#pragma unroll
                for (int cc2 = 0; cc2 < 4; cc2++)
                    acc[r][cc2] = fmaf(av[r], bv[cc2], acc[r][cc2]);
        }
        __syncthreads();
    }

#pragma unroll
    for (int r = 0; r < 4; r++) {
        float bv = BIAS ? bias[o0 + ty * 4 + r] : 0.f;
        float4 v = make_float4(acc[r][0] + bv, acc[r][1] + bv,
                               acc[r][2] + bv, acc[r][3] + bv);
        *(float4*)(Yb + (size_t)(o0 + ty * 4 + r) * N_ + p0 + tx * 4) = v;
    }
}

// ---------------------------------------------------------------------------
// Per-(b,h,d) L2 norm over the token axis for q and k.
// grid = 8192: id = which*4096 + b*512 + (h*64+d)
// q inv-norm carries the sim scale (x10) folded in.
// ---------------------------------------------------------------------------
__global__ void __launch_bounds__(256) norm_k()
{
    const int id    = blockIdx.x;
    const int which = id >> 12;       // 0 = q, 1 = k
    const int r     = id & 4095;
    const int b     = r >> 9;
    const int hd    = r & 511;

    const float* src = g_qkv + ((size_t)b * O3_ + which * HID_ + hd) * N_;

    float s = 0.f;
    for (int i = threadIdx.x; i < N_; i += 256) {
        float v = src[i];
        s = fmaf(v, v, s);
    }
#pragma unroll
    for (int off = 16; off; off >>= 1)
        s += __shfl_xor_sync(0xffffffffu, s, off);

    __shared__ float red[8];
    if ((threadIdx.x & 31) == 0) red[threadIdx.x >> 5] = s;
    __syncthreads();
    if (threadIdx.x == 0) {
        float t = 0.f;
#pragma unroll
        for (int w = 0; w < 8; w++) t += red[w];
        float iv = (which == 0 ? SCALE_ : 1.f) / fmaxf(sqrtf(t), EPS_);
        g_inv[id] = iv;
    }
}

// ---------------------------------------------------------------------------
// Fused flash-style attention per (b, h, 64-query tile).
// q,k,v live in g_qkv as [d][n] per head; norms folded in on tile load.
// Online softmax over 16 key tiles of 64; output written as [h*64+d][n].
// ---------------------------------------------------------------------------
__global__ void __launch_bounds__(256, 3) attn_k()
{
    const int b  = blockIdx.z;
    const int h  = blockIdx.y;
    const int i0 = blockIdx.x * 64;

    const float* qb = g_qkv + ((size_t)b * O3_ + h * 64) * N_;
    const float* kb = g_qkv + ((size_t)b * O3_ + HID_ + h * 64) * N_;
    const float* vb = g_qkv + ((size_t)b * O3_ + 2 * HID_ + h * 64) * N_;
    const float* qin = g_inv + b * HID_ + h * 64;            // q inv norms (xSCALE)
    const float* kin = g_inv + 4096 + b * HID_ + h * 64;     // k inv norms

    __shared__ float Qs[64][64];   // [d][i]
    __shared__ float Ks[64][64];   // [d][j]
    __shared__ float Vs[64][65];   // [d][j] (+1 pad for conflict-free column reads)
    __shared__ float Ps[64][64];   // [j][i]

    const int tid = threadIdx.x;
    const int ty = tid >> 4;   // i group
    const int tx = tid & 15;   // j group (S phase) / d group (PV phase)

    // Load Q tile (coalesced along i), fold q inv-norm (includes x10 scale)
#pragma unroll
    for (int rep = 0; rep < 16; rep++) {
        int idx = rep * 256 + tid;
        int d = idx >> 6, i = idx & 63;
        Qs[d][i] = qb[(size_t)d * N_ + i0 + i] * qin[d];
    }

    float m[4], l[4], O[4][4];
#pragma unroll
    for (int r = 0; r < 4; r++) {
        m[r] = -INFINITY;
        l[r] = 0.f;
#pragma unroll
        for (int c = 0; c < 4; c++) O[r][c] = 0.f;
    }

    for (int j0 = 0; j0 < N_; j0 += 64) {
        // Load K (with inv-norm) and V tiles
#pragma unroll
        for (int rep = 0; rep < 16; rep++) {
            int idx = rep * 256 + tid;
            int d = idx >> 6, j = idx & 63;
            Ks[d][j] = kb[(size_t)d * N_ + j0 + j] * kin[d];
            Vs[d][j] = vb[(size_t)d * N_ + j0 + j];
        }
        __syncthreads();

        // S[i][j] = sum_d Qs[d][i]*Ks[d][j]
        float S[4][4];
#pragma unroll
        for (int r = 0; r < 4; r++)
#pragma unroll
            for (int c = 0; c < 4; c++) S[r][c] = 0.f;

#pragma unroll 16
        for (int d = 0; d < 64; d++) {
            float4 a  = *(const float4*)&Qs[d][ty * 4];
            float4 bb = *(const float4*)&Ks[d][tx * 4];
            float av[4] = {a.x, a.y, a.z, a.w};
            float bv[4] = {bb.x, bb.y, bb.z, bb.w};
#pragma unroll
            for (int r = 0; r < 4; r++)
#pragma unroll
                for (int c = 0; c < 4; c++)
                    S[r][c] = fmaf(av[r], bv[c], S[r][c]);
        }

        // Online softmax. Row i spans the 16 tx lanes (lane bits 0..3).
        float mr[4];
#pragma unroll
        for (int r = 0; r < 4; r++) {
            mr[r] = fmaxf(fmaxf(S[r][0], S[r][1]), fmaxf(S[r][2], S[r][3]));
#pragma unroll
            for (int off = 1; off < 16; off <<= 1)
                mr[r] = fmaxf(mr[r], __shfl_xor_sync(0xffffffffu, mr[r], off));
        }
        float corr[4], ps[4];
#pragma unroll
        for (int r = 0; r < 4; r++) {
            float mn = fmaxf(m[r], mr[r]);
            corr[r] = __expf(m[r] - mn);
            m[r] = mn;
            float s = 0.f;
#pragma unroll
            for (int c = 0; c < 4; c++) {
                S[r][c] = __expf(S[r][c] - mn);
                s += S[r][c];
            }
            ps[r] = s;
        }
#pragma unroll
        for (int r = 0; r < 4; r++) {
#pragma unroll
            for (int off = 1; off < 16; off <<= 1)
                ps[r] += __shfl_xor_sync(0xffffffffu, ps[r], off);
            l[r] = l[r] * corr[r] + ps[r];
#pragma unroll
            for (int c = 0; c < 4; c++) O[r][c] *= corr[r];
        }

        // Stage P transposed: Ps[j][i]
#pragma unroll
        for (int r = 0; r < 4; r++)
#pragma unroll
            for (int c = 0; c < 4; c++)
                Ps[tx * 4 + c][ty * 4 + r] = S[r][c];
        __syncthreads();

        // O[i][d] += sum_j Ps[j][i] * Vs[d][j]   (tx indexes d here)
#pragma unroll 16
        for (int j = 0; j < 64; j++) {
            float4 p = *(const float4*)&Ps[j][ty * 4];
            float pv[4] = {p.x, p.y, p.z, p.w};
            float vv[4];
#pragma unroll
            for (int c = 0; c < 4; c++) vv[c] = Vs[tx * 4 + c][j];
#pragma unroll
            for (int r = 0; r < 4; r++)
#pragma unroll
                for (int c = 0; c < 4; c++)
                    O[r][c] = fmaf(pv[r], vv[c], O[r][c]);
        }
        __syncthreads();
    }

    // Epilogue: divide by l, stage into Qs as [d][i], write coalesced
#pragma unroll
    for (int r = 0; r < 4; r++) {
        float invl = 1.f / l[r];
#pragma unroll
        for (int c = 0; c < 4; c++)
            Qs[tx * 4 + c][ty * 4 + r] = O[r][c] * invl;
    }
    __syncthreads();

    float* ob = g_att + ((size_t)b * HID_ + h * 64) * N_;
#pragma unroll
    for (int rep = 0; rep < 16; rep++) {
        int idx = rep * 256 + tid;
        int d = idx >> 6, i = idx & 63;
        ob[(size_t)d * N_ + i0 + i] = Qs[d][i];
    }
}

// ---------------------------------------------------------------------------
extern "C" void kernel_launch(void* const* d_in, const int* in_sizes, int n_in,
                              void* d_out, int out_size)
{
    (void)in_sizes; (void)n_in; (void)out_size;
    const float* x     = (const float*)d_in[0];  // (8,256,32,32)
    const float* w_qkv = (const float*)d_in[1];  // (1536,256)
    const float* w_out = (const float*)d_in[2];  // (256,512)
    const float* b_out = (const float*)d_in[3];  // (256,)
    float* y = (float*)d_out;                    // (8,256,32,32)

    float* qkv_p = nullptr;
    float* att_p = nullptr;
    cudaGetSymbolAddress((void**)&qkv_p, g_qkv);
    cudaGetSymbolAddress((void**)&att_p, g_att);

    // 1) QKV projection: [1536x256] @ [256x1024] per batch
    gemm_k<O3_, C_, false><<<dim3(N_ / 64, O3_ / 64, B_), 256>>>(
        w_qkv, x, nullptr, qkv_p);

    // 2) Token-axis L2 norms for q and k
    norm_k<<<2 * B_ * HID_, 256>>>();

    // 3) Fused attention
    attn_k<<<dim3(N_ / 64, H_, B_), 256>>>();

    // 4) Output projection + bias: [256x512] @ [512x1024] per batch
    gemm_k<C_, HID_, true><<<dim3(N_ / 64, C_ / 64, B_), 256>>>(
        w_out, att_p, b_out, y);
}

// round 2
// speedup vs baseline: 3.1544x; 3.1544x over previous
#include <cuda_runtime.h>
#include <math.h>
#include <stdint.h>

#define B_    8
#define C_    256
#define N_    1024
#define H_    8
#define HID_  512
#define O3_   1536
#define SCALE_ 10.0f
#define EPS_   1e-12f

// Scratch (static device arrays; no allocation allowed)
__device__ float g_qkv[(size_t)B_ * O3_ * N_];   // [b][o][p]
__device__ float g_inv[2 * B_ * HID_];           // [q/k][b][h*64+d]
__device__ float g_att[(size_t)B_ * HID_ * N_];  // [b][h*64+d][p]

__device__ __forceinline__ uint32_t f2tf(float f) {
    uint32_t r; asm("cvt.rna.tf32.f32 %0, %1;" : "=r"(r) : "f"(f)); return r;
}
__device__ __forceinline__ void mma8(float* d, const uint32_t* a, const uint32_t* b) {
    asm volatile("mma.sync.aligned.m16n8k8.row.col.f32.tf32.tf32.f32 "
                 "{%0,%1,%2,%3}, {%4,%5,%6,%7}, {%8,%9}, {%0,%1,%2,%3};\n"
                 : "+f"(d[0]), "+f"(d[1]), "+f"(d[2]), "+f"(d[3])
                 : "r"(a[0]), "r"(a[1]), "r"(a[2]), "r"(a[3]),
                   "r"(b[0]), "r"(b[1]));
}

// ---------------------------------------------------------------------------
// tf32 tensor-core GEMM: Y[b][o][p] = sum_c W[o][c] * X[b][c][p] (+bias)
// Block tile 128(M) x 64(N), K-tile 32. 8 warps in 4x2 grid, warp tile 32x32.
// ---------------------------------------------------------------------------
template <int M, int K, bool BIAS>
__global__ void __launch_bounds__(256) gemm_tc(const float* __restrict__ W,
                                               const float* __restrict__ X,
                                               const float* __restrict__ bias,
                                               float* __restrict__ Y)
{
    __shared__ uint32_t As[128 * 36];  // [m][k], stride 36 -> frag reads conflict-free
    __shared__ uint32_t Bs[32 * 72];   // [k][n], stride 72 -> frag reads conflict-free

    const int b  = blockIdx.z;
    const int o0 = blockIdx.y * 128;
    const int p0 = blockIdx.x * 64;
    const float* Xb = X + (size_t)b * K * N_;
    float*       Yb = Y + (size_t)b * M * N_;

    const int tid  = threadIdx.x;
    const int warp = tid >> 5;
    const int lane = tid & 31;
    const int g = lane >> 2, c = lane & 3;
    const int wm = (warp >> 1) * 32;
    const int wn = (warp & 1) * 32;

    float acc[2][4][4];
#pragma unroll
    for (int mt = 0; mt < 2; mt++)
#pragma unroll
        for (int nt = 0; nt < 4; nt++)
#pragma unroll
            for (int q = 0; q < 4; q++) acc[mt][nt][q] = 0.f;

    for (int k0 = 0; k0 < K; k0 += 32) {
        // A tile: 128 x 32 (cvt to tf32)
#pragma unroll
        for (int rep = 0; rep < 4; rep++) {
            int lin = rep * 256 + tid;
            int m = lin >> 3, kq = (lin & 7) * 4;
            float4 w4 = *(const float4*)(W + (size_t)(o0 + m) * K + k0 + kq);
            *(uint4*)&As[m * 36 + kq] =
                make_uint4(f2tf(w4.x), f2tf(w4.y), f2tf(w4.z), f2tf(w4.w));
        }
        // B tile: 32 x 64
#pragma unroll
        for (int rep = 0; rep < 2; rep++) {
            int lin = rep * 256 + tid;
            int k = lin >> 4, nq = (lin & 15) * 4;
            float4 x4 = *(const float4*)(Xb + (size_t)(k0 + k) * N_ + p0 + nq);
            *(uint4*)&Bs[k * 72 + nq] =
                make_uint4(f2tf(x4.x), f2tf(x4.y), f2tf(x4.z), f2tf(x4.w));
        }
        __syncthreads();

#pragma unroll
        for (int ks = 0; ks < 32; ks += 8) {
            uint32_t a[2][4];
#pragma unroll
            for (int mt = 0; mt < 2; mt++) {
                int mr = wm + mt * 16;
                a[mt][0] = As[(mr + g) * 36 + ks + c];
                a[mt][1] = As[(mr + g + 8) * 36 + ks + c];
                a[mt][2] = As[(mr + g) * 36 + ks + c + 4];
                a[mt][3] = As[(mr + g + 8) * 36 + ks + c + 4];
            }
#pragma unroll
            for (int nt = 0; nt < 4; nt++) {
                uint32_t bf[2];
                bf[0] = Bs[(ks + c) * 72 + wn + nt * 8 + g];
                bf[1] = Bs[(ks + c + 4) * 72 + wn + nt * 8 + g];
                mma8(acc[0][nt], a[0], bf);
                mma8(acc[1][nt], a[1], bf);
            }
        }
        __syncthreads();
    }

#pragma unroll
    for (int mt = 0; mt < 2; mt++) {
        int r0 = o0 + wm + mt * 16 + g;
        float bv0 = BIAS ? bias[r0] : 0.f;
        float bv1 = BIAS ? bias[r0 + 8] : 0.f;
#pragma unroll
        for (int nt = 0; nt < 4; nt++) {
            int col = p0 + wn + nt * 8 + 2 * c;
            *(float2*)(Yb + (size_t)r0 * N_ + col) =
                make_float2(acc[mt][nt][0] + bv0, acc[mt][nt][1] + bv0);
            *(float2*)(Yb + (size_t)(r0 + 8) * N_ + col) =
                make_float2(acc[mt][nt][2] + bv1, acc[mt][nt][3] + bv1);
        }
    }
}

// ---------------------------------------------------------------------------
// Per-(b,h,d) L2 norm over token axis (q gets x10 scale folded in).
// ---------------------------------------------------------------------------
__global__ void __launch_bounds__(256) norm_k()
{
    const int id    = blockIdx.x;
    const int which = id >> 12;
    const int r     = id & 4095;
    const int b     = r >> 9;
    const int hd    = r & 511;

    const float* src = g_qkv + ((size_t)b * O3_ + which * HID_ + hd) * N_;

    float s = 0.f;
    for (int i = threadIdx.x; i < N_; i += 256) {
        float v = src[i];
        s = fmaf(v, v, s);
    }
#pragma unroll
    for (int off = 16; off; off >>= 1)
        s += __shfl_xor_sync(0xffffffffu, s, off);

    __shared__ float red[8];
    if ((threadIdx.x & 31) == 0) red[threadIdx.x >> 5] = s;
    __syncthreads();
    if (threadIdx.x == 0) {
        float t = 0.f;
#pragma unroll
        for (int w = 0; w < 8; w++) t += red[w];
        g_inv[id] = (which == 0 ? SCALE_ : 1.f) / fmaxf(sqrtf(t), EPS_);
    }
}

// ---------------------------------------------------------------------------
// Fused flash attention, tf32 tensor cores.
// CTA = (b, h, 128-query tile). 8 warps, 16 query rows each.
// Smem layouts: Qs [d][i] stride 136, Ks [d][j] stride 72, Vs [d][j] stride 68,
// Ps [i][j] stride 68 — all mma fragment reads bank-conflict-free.
// ---------------------------------------------------------------------------
#define ATTN_SMEM_U32 (64 * 136 + 64 * 72 + 64 * 68 + 128 * 68)

__global__ void __launch_bounds__(256, 2) attn_tc()
{
    extern __shared__ uint32_t smem_u[];
    uint32_t* Qs = smem_u;             // [64][136]
    uint32_t* Ks = Qs + 64 * 136;      // [64][72]
    uint32_t* Vs = Ks + 64 * 72;       // [64][68]
    uint32_t* Ps = Vs + 64 * 68;       // [128][68]

    const int b = blockIdx.z, h = blockIdx.y, i0 = blockIdx.x * 128;
    const float* qb  = g_qkv + ((size_t)b * O3_ + h * 64) * N_;
    const float* kb  = qb + (size_t)HID_ * N_;
    const float* vb  = qb + (size_t)2 * HID_ * N_;
    const float* qin = g_inv + b * HID_ + h * 64;
    const float* kin = qin + 4096;

    const int tid  = threadIdx.x;
    const int warp = tid >> 5, lane = tid & 31;
    const int g = lane >> 2, c = lane & 3;
    const int wb = warp * 16;  // warp's query-row base within tile

    // Load Q tile [d][i], fold q inv-norm (x10 scale included)
#pragma unroll
    for (int rep = 0; rep < 8; rep++) {
        int lin = rep * 256 + tid;
        int d = lin >> 5, iq = (lin & 31) * 4;
        float s = qin[d];
        float4 q4 = *(const float4*)(qb + (size_t)d * N_ + i0 + iq);
        *(uint4*)&Qs[d * 136 + iq] =
            make_uint4(f2tf(q4.x * s), f2tf(q4.y * s), f2tf(q4.z * s), f2tf(q4.w * s));
    }

    float m[2] = {-INFINITY, -INFINITY}, l[2] = {0.f, 0.f};
    float O[8][4];
#pragma unroll
    for (int dt = 0; dt < 8; dt++)
#pragma unroll
        for (int q = 0; q < 4; q++) O[dt][q] = 0.f;

    for (int j0 = 0; j0 < N_; j0 += 64) {
        // Load K (with inv-norm) and V tiles, [d][j]
#pragma unroll
        for (int rep = 0; rep < 4; rep++) {
            int lin = rep * 256 + tid;
            int d = lin >> 4, jq = (lin & 15) * 4;
            float s = kin[d];
            float4 k4 = *(const float4*)(kb + (size_t)d * N_ + j0 + jq);
            *(uint4*)&Ks[d * 72 + jq] =
                make_uint4(f2tf(k4.x * s), f2tf(k4.y * s), f2tf(k4.z * s), f2tf(k4.w * s));
            float4 v4 = *(const float4*)(vb + (size_t)d * N_ + j0 + jq);
            *(uint4*)&Vs[d * 68 + jq] =
                make_uint4(f2tf(v4.x), f2tf(v4.y), f2tf(v4.z), f2tf(v4.w));
        }
        __syncthreads();

        // S = Q.K^T for this warp's 16 rows x 64 keys
        float S[8][4];
#pragma unroll
        for (int nt = 0; nt < 8; nt++)
#pragma unroll
            for (int q = 0; q < 4; q++) S[nt][q] = 0.f;

#pragma unroll
        for (int ks = 0; ks < 64; ks += 8) {
            uint32_t a[4];
            a[0] = Qs[(ks + c) * 136 + wb + g];
            a[1] = Qs[(ks + c) * 136 + wb + g + 8];
            a[2] = Qs[(ks + c + 4) * 136 + wb + g];
            a[3] = Qs[(ks + c + 4) * 136 + wb + g + 8];
#pragma unroll
            for (int nt = 0; nt < 8; nt++) {
                uint32_t bf[2];
                bf[0] = Ks[(ks + c) * 72 + nt * 8 + g];
                bf[1] = Ks[(ks + c + 4) * 72 + nt * 8 + g];
                mma8(S[nt], a, bf);
            }
        }

        // Online softmax (row slot 0 = row g, slot 1 = row g+8; stats shared
        // across the 4-lane quad via shfl xor 1,2)
        float mloc[2] = {-INFINITY, -INFINITY};
#pragma unroll
        for (int nt = 0; nt < 8; nt++) {
            mloc[0] = fmaxf(mloc[0], fmaxf(S[nt][0], S[nt][1]));
            mloc[1] = fmaxf(mloc[1], fmaxf(S[nt][2], S[nt][3]));
        }
        float corr[2], psum[2];
#pragma unroll
        for (int s_ = 0; s_ < 2; s_++) {
            mloc[s_] = fmaxf(mloc[s_], __shfl_xor_sync(0xffffffffu, mloc[s_], 1));
            mloc[s_] = fmaxf(mloc[s_], __shfl_xor_sync(0xffffffffu, mloc[s_], 2));
            float mn = fmaxf(m[s_], mloc[s_]);
            corr[s_] = __expf(m[s_] - mn);
            m[s_] = mn;
            psum[s_] = 0.f;
        }
#pragma unroll
        for (int nt = 0; nt < 8; nt++) {
            S[nt][0] = __expf(S[nt][0] - m[0]);
            S[nt][1] = __expf(S[nt][1] - m[0]);
            S[nt][2] = __expf(S[nt][2] - m[1]);
            S[nt][3] = __expf(S[nt][3] - m[1]);
            psum[0] += S[nt][0] + S[nt][1];
            psum[1] += S[nt][2] + S[nt][3];
        }
#pragma unroll
        for (int s_ = 0; s_ < 2; s_++) {
            psum[s_] += __shfl_xor_sync(0xffffffffu, psum[s_], 1);
            psum[s_] += __shfl_xor_sync(0xffffffffu, psum[s_], 2);
            l[s_] = l[s_] * corr[s_] + psum[s_];
        }
#pragma unroll
        for (int dt = 0; dt < 8; dt++) {
            O[dt][0] *= corr[0]; O[dt][1] *= corr[0];
            O[dt][2] *= corr[1]; O[dt][3] *= corr[1];
        }

        // Stage P (tf32) into warp-private rows of Ps [i][j]
#pragma unroll
        for (int nt = 0; nt < 8; nt++) {
            *(uint2*)&Ps[(wb + g) * 68 + nt * 8 + 2 * c] =
                make_uint2(f2tf(S[nt][0]), f2tf(S[nt][1]));
            *(uint2*)&Ps[(wb + g + 8) * 68 + nt * 8 + 2 * c] =
                make_uint2(f2tf(S[nt][2]), f2tf(S[nt][3]));
        }
        __syncwarp();

        // O += P.V  (k-dim = j, n-dim = d)
#pragma unroll
        for (int jt = 0; jt < 8; jt++) {
            uint32_t a[4];
            a[0] = Ps[(wb + g) * 68 + jt * 8 + c];
            a[1] = Ps[(wb + g + 8) * 68 + jt * 8 + c];
            a[2] = Ps[(wb + g) * 68 + jt * 8 + c + 4];
            a[3] = Ps[(wb + g + 8) * 68 + jt * 8 + c + 4];
#pragma unroll
            for (int dt = 0; dt < 8; dt++) {
                uint32_t bf[2];
                bf[0] = Vs[(dt * 8 + g) * 68 + jt * 8 + c];
                bf[1] = Vs[(dt * 8 + g) * 68 + jt * 8 + c + 4];
                mma8(O[dt], a, bf);
            }
        }
        __syncthreads();
    }

    // Epilogue: O /= l, stage as [d][i] into Qs region, write coalesced
    float invl0 = 1.f / l[0], invl1 = 1.f / l[1];
    float* Os = (float*)Qs;  // [64][136]
#pragma unroll
    for (int dt = 0; dt < 8; dt++) {
        int d0 = dt * 8 + 2 * c;
        Os[d0 * 136 + wb + g]           = O[dt][0] * invl0;
        Os[(d0 + 1) * 136 + wb + g]     = O[dt][1] * invl0;
        Os[d0 * 136 + wb + g + 8]       = O[dt][2] * invl1;
        Os[(d0 + 1) * 136 + wb + g + 8] = O[dt][3] * invl1;
    }
    __syncthreads();

    float* ob = g_att + ((size_t)b * HID_ + h * 64) * N_;
#pragma unroll
    for (int rep = 0; rep < 8; rep++) {
        int lin = rep * 256 + tid;
        int d = lin >> 5, iq = (lin & 31) * 4;
        *(float4*)(ob + (size_t)d * N_ + i0 + iq) = *(const float4*)&Os[d * 136 + iq];
    }
}

// ---------------------------------------------------------------------------
extern "C" void kernel_launch(void* const* d_in, const int* in_sizes, int n_in,
                              void* d_out, int out_size)
{
    (void)in_sizes; (void)n_in; (void)out_size;
    const float* x     = (const float*)d_in[0];
    const float* w_qkv = (const float*)d_in[1];
    const float* w_out = (const float*)d_in[2];
    const float* b_out = (const float*)d_in[3];
    float* y = (float*)d_out;

    float* qkv_p = nullptr;
    float* att_p = nullptr;
    cudaGetSymbolAddress((void**)&qkv_p, g_qkv);
    cudaGetSymbolAddress((void**)&att_p, g_att);

    cudaFuncSetAttribute(attn_tc, cudaFuncAttributeMaxDynamicSharedMemorySize,
                         ATTN_SMEM_U32 * 4);

    // 1) QKV projection
    gemm_tc<O3_, C_, false><<<dim3(N_ / 64, O3_ / 128, B_), 256>>>(
        w_qkv, x, nullptr, qkv_p);

    // 2) Token-axis L2 norms
    norm_k<<<2 * B_ * HID_, 256>>>();

    // 3) Fused attention
    attn_tc<<<dim3(N_ / 128, H_, B_), 256, ATTN_SMEM_U32 * 4>>>();

    // 4) Output projection + bias
    gemm_tc<C_, HID_, true><<<dim3(N_ / 64, C_ / 128, B_), 256>>>(
        w_out, att_p, b_out, y);
}